// round 5
// baseline (speedup 1.0000x reference)
#include <cuda_runtime.h>

#define NN 100000
#define EE 800000
#define DD 64

// Scratch (allocation-free rule: __device__ globals).
// g_g has ONE EXTRA ROW (index NN) that is never written -> stays zero from
// static init; used as a gather target for padding lanes (branch-free inner loop).
__device__ float g_g[(NN + 1) * DD];
__device__ float g_x[NN * DD];      // ping-pong x between rounds
__device__ int   g_deg[NN];
__device__ int   g_rowptr[NN + 1];
__device__ int   g_cursor[NN];
__device__ int   g_col[EE];
__device__ float g_dis[NN];

// ---------------- CSR build ----------------

__global__ void k_zero(int n) {
    int i = blockIdx.x * blockDim.x + threadIdx.x;
    if (i < n) g_deg[i] = 0;
}

__global__ void k_hist(const int* __restrict__ dst, int e) {
    int i = blockIdx.x * blockDim.x + threadIdx.x;
    if (i < e) atomicAdd(&g_deg[dst[i]], 1);
}

// Single-block exclusive scan over deg -> rowptr/cursor; also dis = rsqrt(deg+1)
__global__ void k_scan(int n) {
    __shared__ int part[1024];
    int t = threadIdx.x;
    int C = (n + 1023) / 1024;
    int lo = t * C;
    int hi = min(lo + C, n);
    int s = 0;
    for (int i = lo; i < hi; i++) s += g_deg[i];
    part[t] = s;
    __syncthreads();
    for (int off = 1; off < 1024; off <<= 1) {
        int v = (t >= off) ? part[t - off] : 0;
        __syncthreads();
        part[t] += v;
        __syncthreads();
    }
    int run = (t == 0) ? 0 : part[t - 1];
    for (int i = lo; i < hi; i++) {
        int d = g_deg[i];
        g_rowptr[i] = run;
        g_cursor[i] = run;
        g_dis[i] = rsqrtf((float)(d + 1));   // +1 self-loop
        run += d;
    }
    if (t == 1023) g_rowptr[n] = run;
}

__global__ void k_scatter(const int* __restrict__ src, const int* __restrict__ dst, int e) {
    int i = blockIdx.x * blockDim.x + threadIdx.x;
    if (i < e) {
        int d = dst[i];
        int pos = atomicAdd(&g_cursor[d], 1);
        g_col[pos] = src[i];
    }
}

// ---------------- per-round kernels ----------------

// g = dis[r] * (x @ W).  Block computes a 64x64 tile. 256 threads, 4x4 outputs each.
// (Proven ~FFMA-floor kernel; only writes rows < n, so pad row NN stays zero.)
__global__ __launch_bounds__(256) void k_gemm(const float* __restrict__ x,
                                              const float* __restrict__ W, int n) {
    __shared__ float Wsh[DD * DD];      // [k][c]
    __shared__ float Xsh[DD * DD];      // [r][k]

    int t = threadIdx.x;
    int rowbase = blockIdx.x * 64;

    {
        const float4* W4 = (const float4*)W;
        float4* Ws4 = (float4*)Wsh;
        #pragma unroll
        for (int i = t; i < 1024; i += 256) Ws4[i] = W4[i];
    }
    {
        float4* Xs4 = (float4*)Xsh;
        #pragma unroll
        for (int i = t; i < 1024; i += 256) {
            int r = i >> 4, k4 = i & 15;
            float4 v = make_float4(0.f, 0.f, 0.f, 0.f);
            if (rowbase + r < n)
                v = ((const float4*)(x + (size_t)(rowbase + r) * DD))[k4];
            Xs4[i] = v;
        }
    }
    __syncthreads();

    int tx = t & 15;
    int ty = t >> 4;

    float acc[4][4];
    #pragma unroll
    for (int i = 0; i < 4; i++)
        #pragma unroll
        for (int j = 0; j < 4; j++) acc[i][j] = 0.f;

    #pragma unroll 8
    for (int k = 0; k < 64; k++) {
        float4 w = ((const float4*)(Wsh + k * DD))[tx];
        float a0 = Xsh[(ty * 4 + 0) * DD + k];
        float a1 = Xsh[(ty * 4 + 1) * DD + k];
        float a2 = Xsh[(ty * 4 + 2) * DD + k];
        float a3 = Xsh[(ty * 4 + 3) * DD + k];
        acc[0][0] += a0 * w.x; acc[0][1] += a0 * w.y; acc[0][2] += a0 * w.z; acc[0][3] += a0 * w.w;
        acc[1][0] += a1 * w.x; acc[1][1] += a1 * w.y; acc[1][2] += a1 * w.z; acc[1][3] += a1 * w.w;
        acc[2][0] += a2 * w.x; acc[2][1] += a2 * w.y; acc[2][2] += a2 * w.z; acc[2][3] += a2 * w.w;
        acc[3][0] += a3 * w.x; acc[3][1] += a3 * w.y; acc[3][2] += a3 * w.z; acc[3][3] += a3 * w.w;
    }

    #pragma unroll
    for (int i = 0; i < 4; i++) {
        int r = rowbase + ty * 4 + i;
        if (r < n) {
            float d = g_dis[r];
            float4 o = make_float4(acc[i][0] * d, acc[i][1] * d, acc[i][2] * d, acc[i][3] * d);
            ((float4*)(g_g + (size_t)r * DD))[tx] = o;
        }
    }
}

// Warp per node (fully converged). Branch-free inner loop: out-of-range slots
// gather the permanently-zero pad row NN, so every block is 8 independent LDG.64s.
//   agg[v] = dis[v] * (sum_{u->v} g[u] + g[v]) + b, then LayerNorm -> out
__global__ __launch_bounds__(256) void k_agg_ln(const float* __restrict__ b,
                                                const float* __restrict__ gamma,
                                                const float* __restrict__ beta,
                                                float* __restrict__ out, int n) {
    int v    = (blockIdx.x * blockDim.x + threadIdx.x) >> 5;
    int lane = threadIdx.x & 31;
    if (v >= n) return;

    const float2* g2 = (const float2*)g_g;
    int rp0 = g_rowptr[v];
    int rp1 = g_rowptr[v + 1];
    float dv = g_dis[v];

    float2 acc = __ldg(&g2[(size_t)v * 32 + lane]);   // self-loop g[v]

    for (int base = rp0; base < rp1; base += 32) {
        int j = base + lane;
        int c = (j < rp1) ? g_col[j] : NN;            // pad -> zero row
        int nblk = (min(32, rp1 - base) + 7) >> 3;    // 1..4, warp-uniform
        for (int bk = 0; bk < nblk; bk++) {
            int s = bk * 8;
            int u0 = __shfl_sync(0xffffffffu, c, s + 0);
            int u1 = __shfl_sync(0xffffffffu, c, s + 1);
            int u2 = __shfl_sync(0xffffffffu, c, s + 2);
            int u3 = __shfl_sync(0xffffffffu, c, s + 3);
            int u4 = __shfl_sync(0xffffffffu, c, s + 4);
            int u5 = __shfl_sync(0xffffffffu, c, s + 5);
            int u6 = __shfl_sync(0xffffffffu, c, s + 6);
            int u7 = __shfl_sync(0xffffffffu, c, s + 7);
            float2 m0 = __ldg(&g2[(size_t)u0 * 32 + lane]);
            float2 m1 = __ldg(&g2[(size_t)u1 * 32 + lane]);
            float2 m2 = __ldg(&g2[(size_t)u2 * 32 + lane]);
            float2 m3 = __ldg(&g2[(size_t)u3 * 32 + lane]);
            float2 m4 = __ldg(&g2[(size_t)u4 * 32 + lane]);
            float2 m5 = __ldg(&g2[(size_t)u5 * 32 + lane]);
            float2 m6 = __ldg(&g2[(size_t)u6 * 32 + lane]);
            float2 m7 = __ldg(&g2[(size_t)u7 * 32 + lane]);
            float px = (m0.x + m1.x) + (m2.x + m3.x);
            float qx = (m4.x + m5.x) + (m6.x + m7.x);
            float py = (m0.y + m1.y) + (m2.y + m3.y);
            float qy = (m4.y + m5.y) + (m6.y + m7.y);
            acc.x += px + qx;
            acc.y += py + qy;
        }
    }

    float2 bb = ((const float2*)b)[lane];
    float a0 = acc.x * dv + bb.x;
    float a1 = acc.y * dv + bb.y;

    // LayerNorm over 64 features (2 per lane, full-warp reduction)
    float s  = a0 + a1;
    float ss = a0 * a0 + a1 * a1;
    #pragma unroll
    for (int o = 16; o > 0; o >>= 1) {
        s  += __shfl_xor_sync(0xffffffffu, s, o);
        ss += __shfl_xor_sync(0xffffffffu, ss, o);
    }
    float mu  = s * (1.f / 64.f);
    float var = ss * (1.f / 64.f) - mu * mu;
    float inv = rsqrtf(var + 1e-5f);

    float2 gm = ((const float2*)gamma)[lane];
    float2 bt = ((const float2*)beta)[lane];
    float2 o2;
    o2.x = (a0 - mu) * inv * gm.x + bt.x;
    o2.y = (a1 - mu) * inv * gm.y + bt.y;
    ((float2*)out)[(size_t)v * 32 + lane] = o2;
}

// ---------------- launch ----------------

extern "C" void kernel_launch(void* const* d_in, const int* in_sizes, int n_in,
                              void* d_out, int out_size) {
    const float* x     = (const float*)d_in[0];
    const int*   ei    = (const int*)d_in[1];
    const float* W     = (const float*)d_in[2];
    const float* b     = (const float*)d_in[3];
    const float* gamma = (const float*)d_in[4];
    const float* beta  = (const float*)d_in[5];

    int n = in_sizes[0] / DD;      // 100000
    int e = in_sizes[1] / 2;       // 800000
    const int* src = ei;
    const int* dst = ei + e;

    k_zero<<<(n + 255) / 256, 256>>>(n);               // kernel 1
    k_hist<<<(e + 255) / 256, 256>>>(dst, e);          // kernel 2
    k_scan<<<1, 1024>>>(n);                            // kernel 3
    k_scatter<<<(e + 255) / 256, 256>>>(src, dst, e);  // kernel 4

    int gemm_blocks = (n + 63) / 64;
    int agg_blocks  = (n + 7) / 8;   // warp per node, 8 warps/block

    const int NUM_ROUNDS = 4;
    for (int r = 0; r < NUM_ROUNDS; r++) {
        const float* xin = (r == 0) ? x : (const float*)g_x;
        float* xout = (r == NUM_ROUNDS - 1) ? (float*)d_out : g_x;
        k_gemm<<<gemm_blocks, 256>>>(xin, W, n);               // kernel 5 on r=0
        k_agg_ln<<<agg_blocks, 256>>>(b, gamma, beta, xout, n); // kernel 6 -> profiled
    }
}

// round 6
// speedup vs baseline: 1.0457x; 1.0457x over previous
#include <cuda_runtime.h>

#define NN 100000
#define EE 800000
#define DD 64

// Scratch (allocation-free rule: __device__ globals).
// g_g has ONE EXTRA ROW (index NN) never written -> stays zero from static
// init; gather target for padding lanes (branch-free inner blocks).
__device__ float g_g[(NN + 1) * DD];
__device__ float g_x[NN * DD];      // ping-pong x between rounds
__device__ int   g_deg[NN];
__device__ int   g_rowptr[NN + 1];
__device__ int   g_cursor[NN];
__device__ int   g_col[EE];
__device__ float g_dis[NN];

// ---------------- CSR build ----------------

__global__ void k_hist(const int* __restrict__ dst, int e) {
    int i = blockIdx.x * blockDim.x + threadIdx.x;
    if (i < e) atomicAdd(&g_deg[dst[i]], 1);
}

// Single-block exclusive scan over deg -> rowptr/cursor; dis = rsqrt(deg+1).
// Re-zeroes g_deg after use so the NEXT launch's k_hist starts from zero
// (initial state is zero from static init -> every launch is identical).
__global__ void k_scan(int n) {
    __shared__ int part[1024];
    int t = threadIdx.x;
    int C = (n + 1023) / 1024;
    int lo = t * C;
    int hi = min(lo + C, n);
    int s = 0;
    for (int i = lo; i < hi; i++) s += g_deg[i];
    part[t] = s;
    __syncthreads();
    for (int off = 1; off < 1024; off <<= 1) {
        int v = (t >= off) ? part[t - off] : 0;
        __syncthreads();
        part[t] += v;
        __syncthreads();
    }
    int run = (t == 0) ? 0 : part[t - 1];
    for (int i = lo; i < hi; i++) {
        int d = g_deg[i];
        g_deg[i] = 0;                        // reset for next launch
        g_rowptr[i] = run;
        g_cursor[i] = run;
        g_dis[i] = rsqrtf((float)(d + 1));   // +1 self-loop
        run += d;
    }
    if (t == 1023) g_rowptr[n] = run;
}

__global__ void k_scatter(const int* __restrict__ src, const int* __restrict__ dst, int e) {
    int i = blockIdx.x * blockDim.x + threadIdx.x;
    if (i < e) {
        int d = dst[i];
        int pos = atomicAdd(&g_cursor[d], 1);
        g_col[pos] = src[i];
    }
}

// ---------------- per-round kernels ----------------

// g = dis[r] * (x @ W). 64x64 tile per block, 256 threads, 4x4 outputs each.
// (~FFMA-floor; writes only rows < n, so pad row NN stays zero.)
__global__ __launch_bounds__(256) void k_gemm(const float* __restrict__ x,
                                              const float* __restrict__ W, int n) {
    __shared__ float Wsh[DD * DD];
    __shared__ float Xsh[DD * DD];

    int t = threadIdx.x;
    int rowbase = blockIdx.x * 64;

    {
        const float4* W4 = (const float4*)W;
        float4* Ws4 = (float4*)Wsh;
        #pragma unroll
        for (int i = t; i < 1024; i += 256) Ws4[i] = W4[i];
    }
    {
        float4* Xs4 = (float4*)Xsh;
        #pragma unroll
        for (int i = t; i < 1024; i += 256) {
            int r = i >> 4, k4 = i & 15;
            float4 v = make_float4(0.f, 0.f, 0.f, 0.f);
            if (rowbase + r < n)
                v = ((const float4*)(x + (size_t)(rowbase + r) * DD))[k4];
            Xs4[i] = v;
        }
    }
    __syncthreads();

    int tx = t & 15;
    int ty = t >> 4;

    float acc[4][4];
    #pragma unroll
    for (int i = 0; i < 4; i++)
        #pragma unroll
        for (int j = 0; j < 4; j++) acc[i][j] = 0.f;

    #pragma unroll 8
    for (int k = 0; k < 64; k++) {
        float4 w = ((const float4*)(Wsh + k * DD))[tx];
        float a0 = Xsh[(ty * 4 + 0) * DD + k];
        float a1 = Xsh[(ty * 4 + 1) * DD + k];
        float a2 = Xsh[(ty * 4 + 2) * DD + k];
        float a3 = Xsh[(ty * 4 + 3) * DD + k];
        acc[0][0] += a0 * w.x; acc[0][1] += a0 * w.y; acc[0][2] += a0 * w.z; acc[0][3] += a0 * w.w;
        acc[1][0] += a1 * w.x; acc[1][1] += a1 * w.y; acc[1][2] += a1 * w.z; acc[1][3] += a1 * w.w;
        acc[2][0] += a2 * w.x; acc[2][1] += a2 * w.y; acc[2][2] += a2 * w.z; acc[2][3] += a2 * w.w;
        acc[3][0] += a3 * w.x; acc[3][1] += a3 * w.y; acc[3][2] += a3 * w.z; acc[3][3] += a3 * w.w;
    }

    #pragma unroll
    for (int i = 0; i < 4; i++) {
        int r = rowbase + ty * 4 + i;
        if (r < n) {
            float d = g_dis[r];
            float4 o = make_float4(acc[i][0] * d, acc[i][1] * d, acc[i][2] * d, acc[i][3] * d);
            ((float4*)(g_g + (size_t)r * DD))[tx] = o;
        }
    }
}

// 4 nodes per warp, software-pipelined. All control warp-uniform, full-mask
// shuffles safe. Pads gather permanent zero row NN.
__global__ __launch_bounds__(256) void k_agg_ln(const float* __restrict__ b,
                                                const float* __restrict__ gamma,
                                                const float* __restrict__ beta,
                                                float* __restrict__ out, int n) {
    int w    = (blockIdx.x * blockDim.x + threadIdx.x) >> 5;
    int lane = threadIdx.x & 31;
    int base = w * 4;
    if (base >= n) return;

    const float2* g2 = (const float2*)g_g;

    // Lane-parallel metadata: rowptr[base..base+4], dis[base..base+3]
    int rr = g_rowptr[min(base + min(lane, 4), n)];
    float dd = g_dis[min(base + min(lane, 3), n - 1)];

    // Issue all 4 col-chunks + 4 self rows up front (independent streams)
    int   c[4];
    float2 acc[4];
    #pragma unroll
    for (int k = 0; k < 4; k++) {
        int rpk  = __shfl_sync(0xffffffffu, rr, k);
        int rpk1 = __shfl_sync(0xffffffffu, rr, k + 1);
        int j = rpk + lane;
        c[k] = (j < rpk1) ? g_col[j] : NN;
        int vk = min(base + k, n - 1);
        acc[k] = g2[(size_t)vk * 32 + lane];
    }

    #define GATHER8(K, S)                                                     \
    {                                                                         \
        int u0 = __shfl_sync(0xffffffffu, c[K], (S) + 0);                     \
        int u1 = __shfl_sync(0xffffffffu, c[K], (S) + 1);                     \
        int u2 = __shfl_sync(0xffffffffu, c[K], (S) + 2);                     \
        int u3 = __shfl_sync(0xffffffffu, c[K], (S) + 3);                     \
        int u4 = __shfl_sync(0xffffffffu, c[K], (S) + 4);                     \
        int u5 = __shfl_sync(0xffffffffu, c[K], (S) + 5);                     \
        int u6 = __shfl_sync(0xffffffffu, c[K], (S) + 6);                     \
        int u7 = __shfl_sync(0xffffffffu, c[K], (S) + 7);                     \
        float2 m0 = g2[(size_t)u0 * 32 + lane];                               \
        float2 m1 = g2[(size_t)u1 * 32 + lane];                               \
        float2 m2 = g2[(size_t)u2 * 32 + lane];                               \
        float2 m3 = g2[(size_t)u3 * 32 + lane];                               \
        float2 m4 = g2[(size_t)u4 * 32 + lane];                               \
        float2 m5 = g2[(size_t)u5 * 32 + lane];                               \
        float2 m6 = g2[(size_t)u6 * 32 + lane];                               \
        float2 m7 = g2[(size_t)u7 * 32 + lane];                               \
        acc[K].x += ((m0.x + m1.x) + (m2.x + m3.x)) + ((m4.x + m5.x) + (m6.x + m7.x)); \
        acc[K].y += ((m0.y + m1.y) + (m2.y + m3.y)) + ((m4.y + m5.y) + (m6.y + m7.y)); \
    }

    // Block 0 unconditional for all 4 nodes: 32 straight-line independent gathers
    #pragma unroll
    for (int k = 0; k < 4; k++) GATHER8(k, 0)

    // Blocks 1..3: warp-uniform predicate per (b,k)
    #pragma unroll
    for (int bb = 1; bb < 4; bb++) {
        #pragma unroll
        for (int k = 0; k < 4; k++) {
            int rpk  = __shfl_sync(0xffffffffu, rr, k);
            int rpk1 = __shfl_sync(0xffffffffu, rr, k + 1);
            if (rpk + bb * 8 < rpk1) GATHER8(k, bb * 8)
        }
    }

    // Rare tail: degree > 32
    #pragma unroll
    for (int k = 0; k < 4; k++) {
        int rpk  = __shfl_sync(0xffffffffu, rr, k);
        int rpk1 = __shfl_sync(0xffffffffu, rr, k + 1);
        for (int start = rpk + 32; start < rpk1; start += 32) {
            int j = start + lane;
            int ct = (j < rpk1) ? g_col[j] : NN;
            int nb = (min(32, rpk1 - start) + 7) >> 3;
            for (int q = 0; q < nb; q++) {
                int s8 = q * 8;
                int u0 = __shfl_sync(0xffffffffu, ct, s8 + 0);
                int u1 = __shfl_sync(0xffffffffu, ct, s8 + 1);
                int u2 = __shfl_sync(0xffffffffu, ct, s8 + 2);
                int u3 = __shfl_sync(0xffffffffu, ct, s8 + 3);
                int u4 = __shfl_sync(0xffffffffu, ct, s8 + 4);
                int u5 = __shfl_sync(0xffffffffu, ct, s8 + 5);
                int u6 = __shfl_sync(0xffffffffu, ct, s8 + 6);
                int u7 = __shfl_sync(0xffffffffu, ct, s8 + 7);
                float2 m0 = g2[(size_t)u0 * 32 + lane];
                float2 m1 = g2[(size_t)u1 * 32 + lane];
                float2 m2 = g2[(size_t)u2 * 32 + lane];
                float2 m3 = g2[(size_t)u3 * 32 + lane];
                float2 m4 = g2[(size_t)u4 * 32 + lane];
                float2 m5 = g2[(size_t)u5 * 32 + lane];
                float2 m6 = g2[(size_t)u6 * 32 + lane];
                float2 m7 = g2[(size_t)u7 * 32 + lane];
                acc[k].x += ((m0.x + m1.x) + (m2.x + m3.x)) + ((m4.x + m5.x) + (m6.x + m7.x));
                acc[k].y += ((m0.y + m1.y) + (m2.y + m3.y)) + ((m4.y + m5.y) + (m6.y + m7.y));
            }
        }
    }

    float2 bb2 = ((const float2*)b)[lane];
    float2 gm  = ((const float2*)gamma)[lane];
    float2 bt  = ((const float2*)beta)[lane];

    // 4 independent LN chains (unrolled -> pipeline with each other)
    float a0[4], a1[4], sum[4], sqs[4];
    #pragma unroll
    for (int k = 0; k < 4; k++) {
        float dv = __shfl_sync(0xffffffffu, dd, k);
        a0[k] = acc[k].x * dv + bb2.x;
        a1[k] = acc[k].y * dv + bb2.y;
        sum[k] = a0[k] + a1[k];
        sqs[k] = a0[k] * a0[k] + a1[k] * a1[k];
    }
    #pragma unroll
    for (int o = 16; o > 0; o >>= 1) {
        #pragma unroll
        for (int k = 0; k < 4; k++) {
            sum[k] += __shfl_xor_sync(0xffffffffu, sum[k], o);
            sqs[k] += __shfl_xor_sync(0xffffffffu, sqs[k], o);
        }
    }
    #pragma unroll
    for (int k = 0; k < 4; k++) {
        int v = base + k;
        if (v < n) {
            float mu  = sum[k] * (1.f / 64.f);
            float var = sqs[k] * (1.f / 64.f) - mu * mu;
            float inv = rsqrtf(var + 1e-5f);
            float2 o2;
            o2.x = (a0[k] - mu) * inv * gm.x + bt.x;
            o2.y = (a1[k] - mu) * inv * gm.y + bt.y;
            ((float2*)out)[(size_t)v * 32 + lane] = o2;
        }
    }
    #undef GATHER8
}

// ---------------- launch ----------------

extern "C" void kernel_launch(void* const* d_in, const int* in_sizes, int n_in,
                              void* d_out, int out_size) {
    const float* x     = (const float*)d_in[0];
    const int*   ei    = (const int*)d_in[1];
    const float* W     = (const float*)d_in[2];
    const float* b     = (const float*)d_in[3];
    const float* gamma = (const float*)d_in[4];
    const float* beta  = (const float*)d_in[5];

    int n = in_sizes[0] / DD;      // 100000
    int e = in_sizes[1] / 2;       // 800000
    const int* src = ei;
    const int* dst = ei + e;

    k_hist<<<(e + 255) / 256, 256>>>(dst, e);          // kernel 1
    k_scan<<<1, 1024>>>(n);                            // kernel 2 (also re-zeroes deg)
    k_scatter<<<(e + 255) / 256, 256>>>(src, dst, e);  // kernel 3

    int gemm_blocks = (n + 63) / 64;
    int agg_blocks  = (n + 31) / 32;   // 4 nodes/warp, 8 warps/block

    const int NUM_ROUNDS = 4;
    for (int r = 0; r < NUM_ROUNDS; r++) {
        const float* xin = (r == 0) ? x : (const float*)g_x;
        float* xout = (r == NUM_ROUNDS - 1) ? (float*)d_out : g_x;
        k_gemm<<<gemm_blocks, 256>>>(xin, W, n);                // kernel 4 on r=0
        k_agg_ln<<<agg_blocks, 256>>>(b, gamma, beta, xout, n); // kernel 5 on r=0
    }
}